// round 6
// baseline (speedup 1.0000x reference)
#include <cuda_runtime.h>

#define N_NODES 40000
#define N_EDGES 640000
#define IN_F    128
#define OUT_F   64
#define NK      8
#define FD      8

// ---------------- persistent device scratch (no allocations allowed) ----------------
__device__ int   g_deg[N_NODES];
__device__ int   g_rowptr[N_NODES + 1];
__device__ int   g_cursor[N_NODES];
__device__ int   g_csrdst[N_EDGES];
__device__ float g_hn[N_NODES * OUT_F];   // h_normed (constant gather table across iters)
__device__ float g_b0[N_NODES * OUT_F];   // h_dst ping
__device__ float g_b1[N_NODES * OUT_F];   // h_dst pong

// ---------------- CSR build ----------------
__global__ void zero_deg_kernel() {
    int i = blockIdx.x * blockDim.x + threadIdx.x;
    if (i < N_NODES) g_deg[i] = 0;
}

// 4 edges per thread via int4 (N_EDGES % 4 == 0)
__global__ void hist_kernel(const int* __restrict__ src) {
    int q = blockIdx.x * blockDim.x + threadIdx.x;
    if (q < N_EDGES / 4) {
        int4 v = __ldg(reinterpret_cast<const int4*>(src) + q);
        atomicAdd(&g_deg[v.x], 1);
        atomicAdd(&g_deg[v.y], 1);
        atomicAdd(&g_deg[v.z], 1);
        atomicAdd(&g_deg[v.w], 1);
    }
}

// Single-block chunked exclusive scan over g_deg -> g_rowptr / g_cursor.
// 1024 threads, 4 elems/thread => 4096/chunk, 10 chunks, warp-shuffle scans.
__global__ void scan_kernel() {
    __shared__ int wsum[32];
    __shared__ int carry_sh;
    int tid  = threadIdx.x;
    int lane = tid & 31, wid = tid >> 5;
    if (tid == 0) carry_sh = 0;
    __syncthreads();

    for (int base = 0; base < N_NODES; base += 4096) {
        int i0 = base + tid * 4;
        int v0 = (i0 + 0 < N_NODES) ? g_deg[i0 + 0] : 0;
        int v1 = (i0 + 1 < N_NODES) ? g_deg[i0 + 1] : 0;
        int v2 = (i0 + 2 < N_NODES) ? g_deg[i0 + 2] : 0;
        int v3 = (i0 + 3 < N_NODES) ? g_deg[i0 + 3] : 0;
        int tsum = v0 + v1 + v2 + v3;

        int incl = tsum;
        #pragma unroll
        for (int off = 1; off < 32; off <<= 1) {
            int u = __shfl_up_sync(0xffffffffu, incl, off);
            if (lane >= off) incl += u;
        }
        if (lane == 31) wsum[wid] = incl;
        __syncthreads();
        if (wid == 0) {
            int wi = wsum[lane];
            #pragma unroll
            for (int off = 1; off < 32; off <<= 1) {
                int u = __shfl_up_sync(0xffffffffu, wi, off);
                if (lane >= off) wi += u;
            }
            wsum[lane] = wi;  // inclusive over warp sums
        }
        __syncthreads();

        int carry   = carry_sh;
        int warpoff = (wid > 0) ? wsum[wid - 1] : 0;
        int ex      = carry + warpoff + (incl - tsum);

        int e0 = ex;
        int e1 = e0 + v0;
        int e2 = e1 + v1;
        int e3 = e2 + v2;
        if (i0 + 0 < N_NODES) { g_rowptr[i0 + 0] = e0; g_cursor[i0 + 0] = e0; }
        if (i0 + 1 < N_NODES) { g_rowptr[i0 + 1] = e1; g_cursor[i0 + 1] = e1; }
        if (i0 + 2 < N_NODES) { g_rowptr[i0 + 2] = e2; g_cursor[i0 + 2] = e2; }
        if (i0 + 3 < N_NODES) { g_rowptr[i0 + 3] = e3; g_cursor[i0 + 3] = e3; }
        __syncthreads();
        if (tid == 0) carry_sh = carry + wsum[31];
        __syncthreads();
    }
    if (threadIdx.x == 0) g_rowptr[N_NODES] = carry_sh;
}

// 4 edges per thread via int4 on both src and dst streams
__global__ void scatter_kernel(const int* __restrict__ src, const int* __restrict__ dst) {
    int q = blockIdx.x * blockDim.x + threadIdx.x;
    if (q < N_EDGES / 4) {
        int4 s4 = __ldg(reinterpret_cast<const int4*>(src) + q);
        int4 d4 = __ldg(reinterpret_cast<const int4*>(dst) + q);
        int p;
        p = atomicAdd(&g_cursor[s4.x], 1); g_csrdst[p] = d4.x;
        p = atomicAdd(&g_cursor[s4.y], 1); g_csrdst[p] = d4.y;
        p = atomicAdd(&g_cursor[s4.z], 1); g_csrdst[p] = d4.z;
        p = atomicAdd(&g_cursor[s4.w], 1); g_csrdst[p] = d4.w;
    }
}

// ---------------- fused GEMM + bias + leaky_relu + per-factor l2norm ----------------
// Block: 256 threads, tile 64 rows x 64 cols, thread = 4x4 register tile.
// K=128 processed in two 64-wide SMEM chunks.
__global__ __launch_bounds__(256) void gemm_norm_kernel(
        const float* __restrict__ x, const float* __restrict__ w,
        const float* __restrict__ bias) {
    __shared__ float xs[64][65];   // x chunk 64 rows x 64 k (padded); reused as out tile
    __shared__ float ws[64][64];   // w chunk 64 k x 64 cols

    int t    = threadIdx.x;
    int row0 = blockIdx.x * 64;
    int tx   = t & 15;     // col group (4 cols)
    int ty   = t >> 4;     // row group (4 rows)

    float acc[4][4];
    #pragma unroll
    for (int i = 0; i < 4; i++)
        #pragma unroll
        for (int j = 0; j < 4; j++) acc[i][j] = 0.0f;

    for (int kc = 0; kc < IN_F; kc += 64) {
        #pragma unroll
        for (int i = 0; i < 4; i++) {
            int li = t + i * 256;           // 0..1023
            int r  = li >> 4;               // 0..63
            int c4 = li & 15;               // 0..15
            float4 v = *reinterpret_cast<const float4*>(x + (size_t)(row0 + r) * IN_F + kc + c4 * 4);
            xs[r][c4 * 4 + 0] = v.x; xs[r][c4 * 4 + 1] = v.y;
            xs[r][c4 * 4 + 2] = v.z; xs[r][c4 * 4 + 3] = v.w;
        }
        #pragma unroll
        for (int i = 0; i < 4; i++) {
            int li = t + i * 256;
            int r  = li >> 4;
            int c4 = li & 15;
            float4 v = *reinterpret_cast<const float4*>(w + (size_t)(kc + r) * OUT_F + c4 * 4);
            *reinterpret_cast<float4*>(&ws[r][c4 * 4]) = v;
        }
        __syncthreads();

        #pragma unroll
        for (int k = 0; k < 64; k++) {
            float4 b = *reinterpret_cast<const float4*>(&ws[k][tx * 4]);
            float a0 = xs[ty * 4 + 0][k];
            float a1 = xs[ty * 4 + 1][k];
            float a2 = xs[ty * 4 + 2][k];
            float a3 = xs[ty * 4 + 3][k];
            acc[0][0] += a0 * b.x; acc[0][1] += a0 * b.y; acc[0][2] += a0 * b.z; acc[0][3] += a0 * b.w;
            acc[1][0] += a1 * b.x; acc[1][1] += a1 * b.y; acc[1][2] += a1 * b.z; acc[1][3] += a1 * b.w;
            acc[2][0] += a2 * b.x; acc[2][1] += a2 * b.y; acc[2][2] += a2 * b.z; acc[2][3] += a2 * b.w;
            acc[3][0] += a3 * b.x; acc[3][1] += a3 * b.y; acc[3][2] += a3 * b.z; acc[3][3] += a3 * b.w;
        }
        __syncthreads();
    }

    // bias + leaky_relu into out tile (reuse xs)
    float4 bv = *reinterpret_cast<const float4*>(bias + tx * 4);
    float bb[4] = {bv.x, bv.y, bv.z, bv.w};
    #pragma unroll
    for (int i = 0; i < 4; i++)
        #pragma unroll
        for (int j = 0; j < 4; j++) {
            float v = acc[i][j] + bb[j];
            v = (v > 0.0f) ? v : 0.01f * v;
            xs[ty * 4 + i][tx * 4 + j] = v;
        }
    __syncthreads();

    // per-factor l2norm: 64 rows x 8 factors = 512 tasks
    for (int p = t; p < 512; p += 256) {
        int r  = p >> 3;
        int kk = p & 7;
        float vreg[8];
        float ss = 0.0f;
        #pragma unroll
        for (int i = 0; i < 8; i++) {
            vreg[i] = xs[r][kk * 8 + i];
            ss += vreg[i] * vreg[i];
        }
        float rs = rsqrtf(ss);
        float* dstp = g_hn + (size_t)(row0 + r) * OUT_F + kk * 8;
        #pragma unroll
        for (int i = 0; i < 8; i++) dstp[i] = vreg[i] * rs;
    }
}

// ---------------- one disentangle iteration (fused softmax + aggregate + residual + norm) ----
// Warp = one node. Lane = (factor k = lane&7, edge-slot j = lane>>3).
// Lane (k,j) accumulates numer/denom for factor k over edges e0+j, e0+j+4, ...
// with the next slot's index prefetched one trip ahead.
//   s = <h_dst[n,k], h_normed[d,k]>  (|s|<=1, so softmax needs no max-subtraction)
// Butterfly shfl_xor (8,16) sums the 4 edge-slots; lanes 0..7 finish:
//   out = l2norm(numer/denom + h_normed[n,k]).
__global__ __launch_bounds__(256) void attn_kernel(int iter, float* __restrict__ out_final) {
    int n = (blockIdx.x * blockDim.x + threadIdx.x) >> 5;
    if (n >= N_NODES) return;
    int lane = threadIdx.x & 31;
    int k = lane & 7;
    int j = lane >> 3;       // 0..3

    const float* hin  = (iter == 0) ? g_hn : ((iter == 1) ? g_b0 : g_b1);
    float*       hout = (iter == 0) ? g_b0 : ((iter == 1) ? g_b1 : out_final);

    const float4* hdr = reinterpret_cast<const float4*>(hin + (size_t)n * OUT_F + k * FD);
    float4 h0 = __ldg(hdr + 0);
    float4 h1 = __ldg(hdr + 1);

    float nu0 = 0.f, nu1 = 0.f, nu2 = 0.f, nu3 = 0.f;
    float nu4 = 0.f, nu5 = 0.f, nu6 = 0.f, nu7 = 0.f;
    float den = 0.f;

    int e0 = __ldg(&g_rowptr[n]);
    int e1 = __ldg(&g_rowptr[n + 1]);

    int e = e0 + j;
    int d_cur = (e < e1) ? __ldg(&g_csrdst[e]) : 0;
    for (; e < e1; e += 4) {
        // prefetch next trip's index while this trip's gather+math is in flight
        int d_nxt = (e + 4 < e1) ? __ldg(&g_csrdst[e + 4]) : 0;

        const float4* fp = reinterpret_cast<const float4*>(g_hn + (size_t)d_cur * OUT_F + k * FD);
        float4 f0 = __ldg(fp + 0);
        float4 f1 = __ldg(fp + 1);

        float s = h0.x * f0.x + h0.y * f0.y + h0.z * f0.z + h0.w * f0.w
                + h1.x * f1.x + h1.y * f1.y + h1.z * f1.z + h1.w * f1.w;
        float ex = __expf(s);
        den += ex;
        nu0 += ex * f0.x; nu1 += ex * f0.y; nu2 += ex * f0.z; nu3 += ex * f0.w;
        nu4 += ex * f1.x; nu5 += ex * f1.y; nu6 += ex * f1.z; nu7 += ex * f1.w;

        d_cur = d_nxt;
    }

    // butterfly reduce across the 4 edge-slots (lanes k, k+8, k+16, k+24)
    #pragma unroll
    for (int m = 8; m <= 16; m <<= 1) {
        den += __shfl_xor_sync(0xffffffffu, den, m);
        nu0 += __shfl_xor_sync(0xffffffffu, nu0, m);
        nu1 += __shfl_xor_sync(0xffffffffu, nu1, m);
        nu2 += __shfl_xor_sync(0xffffffffu, nu2, m);
        nu3 += __shfl_xor_sync(0xffffffffu, nu3, m);
        nu4 += __shfl_xor_sync(0xffffffffu, nu4, m);
        nu5 += __shfl_xor_sync(0xffffffffu, nu5, m);
        nu6 += __shfl_xor_sync(0xffffffffu, nu6, m);
        nu7 += __shfl_xor_sync(0xffffffffu, nu7, m);
    }

    if (lane < 8) {
        float inv = (e1 > e0) ? (1.0f / den) : 0.0f;

        const float4* hnr = reinterpret_cast<const float4*>(g_hn + (size_t)n * OUT_F + k * FD);
        float4 a0 = __ldg(hnr + 0);
        float4 a1 = __ldg(hnr + 1);

        float o0 = nu0 * inv + a0.x;
        float o1 = nu1 * inv + a0.y;
        float o2 = nu2 * inv + a0.z;
        float o3 = nu3 * inv + a0.w;
        float o4 = nu4 * inv + a1.x;
        float o5 = nu5 * inv + a1.y;
        float o6 = nu6 * inv + a1.z;
        float o7 = nu7 * inv + a1.w;

        float ss = o0*o0 + o1*o1 + o2*o2 + o3*o3 + o4*o4 + o5*o5 + o6*o6 + o7*o7;
        float r  = rsqrtf(ss);

        float4* op = reinterpret_cast<float4*>(hout + (size_t)n * OUT_F + k * FD);
        op[0] = make_float4(o0 * r, o1 * r, o2 * r, o3 * r);
        op[1] = make_float4(o4 * r, o5 * r, o6 * r, o7 * r);
    }
}

// ---------------- launch ----------------
extern "C" void kernel_launch(void* const* d_in, const int* in_sizes, int n_in,
                              void* d_out, int out_size) {
    const float* x    = (const float*)d_in[0];   // [40000,128]
    const float* w    = (const float*)d_in[1];   // [128,64]
    const float* bias = (const float*)d_in[2];   // [64]
    const int*   ei   = (const int*)d_in[3];     // [2,640000]
    const int*   src  = ei;
    const int*   dst  = ei + N_EDGES;
    float*       out  = (float*)d_out;           // [40000,64]

    zero_deg_kernel<<<(N_NODES + 255) / 256, 256>>>();
    hist_kernel<<<(N_EDGES / 4 + 255) / 256, 256>>>(src);
    scan_kernel<<<1, 1024>>>();
    scatter_kernel<<<(N_EDGES / 4 + 255) / 256, 256>>>(src, dst);

    gemm_norm_kernel<<<N_NODES / 64, 256>>>(x, w, bias);

    // one warp per node: 40000 warps -> 5000 blocks of 256 threads
    int attn_blocks = (N_NODES * 32 + 255) / 256;
    attn_kernel<<<attn_blocks, 256>>>(0, out);
    attn_kernel<<<attn_blocks, 256>>>(1, out);
    attn_kernel<<<attn_blocks, 256>>>(2, out);
}

// round 7
// speedup vs baseline: 1.1844x; 1.1844x over previous
#include <cuda_runtime.h>

#define N_NODES 40000
#define N_EDGES 640000
#define IN_F    128
#define OUT_F   64
#define NK      8
#define FD      8

#define SCAN_BLK   256
#define N_PART     ((N_NODES + SCAN_BLK - 1) / SCAN_BLK)   // 157

// ---------------- persistent device scratch (no allocations allowed) ----------------
__device__ int   g_deg[N_NODES];
__device__ int   g_rowptr[N_NODES + 1];
__device__ int   g_cursor[N_NODES];
__device__ int   g_csrdst[N_EDGES];
__device__ int   g_part[N_PART];       // per-block partial sums
__device__ int   g_partscan[N_PART];   // exclusive scan of partials
__device__ float g_hn[N_NODES * OUT_F];   // h_normed (constant gather table across iters)
__device__ float g_b0[N_NODES * OUT_F];   // h_dst ping
__device__ float g_b1[N_NODES * OUT_F];   // h_dst pong

// ---------------- CSR build ----------------
__global__ void zero_deg_kernel() {
    int i = blockIdx.x * blockDim.x + threadIdx.x;
    if (i < N_NODES) g_deg[i] = 0;
}

// 1 edge per thread: max resident warps -> max atomics in flight (latency-bound op)
__global__ void hist_kernel(const int* __restrict__ src) {
    int e = blockIdx.x * blockDim.x + threadIdx.x;
    if (e < N_EDGES) atomicAdd(&g_deg[src[e]], 1);
}

// ---- multi-block exclusive scan over g_deg (3 tiny kernels) ----

// block-level exclusive scan helper: returns exclusive prefix of v within the
// block; *total gets the block sum. 256 threads = 8 warps.
__device__ __forceinline__ int block_excl_scan(int v, int* total) {
    __shared__ int wsum[8];
    int lane = threadIdx.x & 31, wid = threadIdx.x >> 5;
    int incl = v;
    #pragma unroll
    for (int off = 1; off < 32; off <<= 1) {
        int u = __shfl_up_sync(0xffffffffu, incl, off);
        if (lane >= off) incl += u;
    }
    if (lane == 31) wsum[wid] = incl;
    __syncthreads();
    if (wid == 0) {
        int wi = (lane < 8) ? wsum[lane] : 0;
        #pragma unroll
        for (int off = 1; off < 8; off <<= 1) {
            int u = __shfl_up_sync(0xffffffffu, wi, off);
            if (lane >= off) wi += u;
        }
        if (lane < 8) wsum[lane] = wi;   // inclusive warp sums
    }
    __syncthreads();
    int warpoff = (wid > 0) ? wsum[wid - 1] : 0;
    *total = wsum[7];
    return warpoff + (incl - v);
}

__global__ void scan_partial_kernel() {
    int i = blockIdx.x * SCAN_BLK + threadIdx.x;
    int v = (i < N_NODES) ? g_deg[i] : 0;
    int total;
    block_excl_scan(v, &total);
    if (threadIdx.x == 0) g_part[blockIdx.x] = total;
}

// single block scans the 157 partials (tiny)
__global__ void scan_part2_kernel() {
    int t = threadIdx.x;
    int v = (t < N_PART) ? g_part[t] : 0;
    int total;
    int ex = block_excl_scan(v, &total);
    if (t < N_PART) g_partscan[t] = ex;
    if (t == 0) g_rowptr[N_NODES] = total;   // = N_EDGES
}

__global__ void scan_apply_kernel() {
    int i = blockIdx.x * SCAN_BLK + threadIdx.x;
    int v = (i < N_NODES) ? g_deg[i] : 0;
    int total;
    int ex = block_excl_scan(v, &total);
    if (i < N_NODES) {
        int val = g_partscan[blockIdx.x] + ex;
        g_rowptr[i] = val;
        g_cursor[i] = val;
    }
}

// 1 edge per thread
__global__ void scatter_kernel(const int* __restrict__ src, const int* __restrict__ dst) {
    int e = blockIdx.x * blockDim.x + threadIdx.x;
    if (e < N_EDGES) {
        int s   = src[e];
        int pos = atomicAdd(&g_cursor[s], 1);
        g_csrdst[pos] = dst[e];
    }
}

// ---------------- fused GEMM + bias + leaky_relu + per-factor l2norm ----------------
// Block: 256 threads, tile 64 rows x 64 cols, thread = 4x4 register tile.
// K=128 processed in two 64-wide SMEM chunks.
__global__ __launch_bounds__(256) void gemm_norm_kernel(
        const float* __restrict__ x, const float* __restrict__ w,
        const float* __restrict__ bias) {
    __shared__ float xs[64][65];   // x chunk 64 rows x 64 k (padded); reused as out tile
    __shared__ float ws[64][64];   // w chunk 64 k x 64 cols

    int t    = threadIdx.x;
    int row0 = blockIdx.x * 64;
    int tx   = t & 15;     // col group (4 cols)
    int ty   = t >> 4;     // row group (4 rows)

    float acc[4][4];
    #pragma unroll
    for (int i = 0; i < 4; i++)
        #pragma unroll
        for (int j = 0; j < 4; j++) acc[i][j] = 0.0f;

    for (int kc = 0; kc < IN_F; kc += 64) {
        #pragma unroll
        for (int i = 0; i < 4; i++) {
            int li = t + i * 256;           // 0..1023
            int r  = li >> 4;               // 0..63
            int c4 = li & 15;               // 0..15
            float4 v = *reinterpret_cast<const float4*>(x + (size_t)(row0 + r) * IN_F + kc + c4 * 4);
            xs[r][c4 * 4 + 0] = v.x; xs[r][c4 * 4 + 1] = v.y;
            xs[r][c4 * 4 + 2] = v.z; xs[r][c4 * 4 + 3] = v.w;
        }
        #pragma unroll
        for (int i = 0; i < 4; i++) {
            int li = t + i * 256;
            int r  = li >> 4;
            int c4 = li & 15;
            float4 v = *reinterpret_cast<const float4*>(w + (size_t)(kc + r) * OUT_F + c4 * 4);
            *reinterpret_cast<float4*>(&ws[r][c4 * 4]) = v;
        }
        __syncthreads();

        #pragma unroll
        for (int k = 0; k < 64; k++) {
            float4 b = *reinterpret_cast<const float4*>(&ws[k][tx * 4]);
            float a0 = xs[ty * 4 + 0][k];
            float a1 = xs[ty * 4 + 1][k];
            float a2 = xs[ty * 4 + 2][k];
            float a3 = xs[ty * 4 + 3][k];
            acc[0][0] += a0 * b.x; acc[0][1] += a0 * b.y; acc[0][2] += a0 * b.z; acc[0][3] += a0 * b.w;
            acc[1][0] += a1 * b.x; acc[1][1] += a1 * b.y; acc[1][2] += a1 * b.z; acc[1][3] += a1 * b.w;
            acc[2][0] += a2 * b.x; acc[2][1] += a2 * b.y; acc[2][2] += a2 * b.z; acc[2][3] += a2 * b.w;
            acc[3][0] += a3 * b.x; acc[3][1] += a3 * b.y; acc[3][2] += a3 * b.z; acc[3][3] += a3 * b.w;
        }
        __syncthreads();
    }

    // bias + leaky_relu into out tile (reuse xs)
    float4 bv = *reinterpret_cast<const float4*>(bias + tx * 4);
    float bb[4] = {bv.x, bv.y, bv.z, bv.w};
    #pragma unroll
    for (int i = 0; i < 4; i++)
        #pragma unroll
        for (int j = 0; j < 4; j++) {
            float v = acc[i][j] + bb[j];
            v = (v > 0.0f) ? v : 0.01f * v;
            xs[ty * 4 + i][tx * 4 + j] = v;
        }
    __syncthreads();

    // per-factor l2norm: 64 rows x 8 factors = 512 tasks
    for (int p = t; p < 512; p += 256) {
        int r  = p >> 3;
        int kk = p & 7;
        float vreg[8];
        float ss = 0.0f;
        #pragma unroll
        for (int i = 0; i < 8; i++) {
            vreg[i] = xs[r][kk * 8 + i];
            ss += vreg[i] * vreg[i];
        }
        float rs = rsqrtf(ss);
        float* dstp = g_hn + (size_t)(row0 + r) * OUT_F + kk * 8;
        #pragma unroll
        for (int i = 0; i < 8; i++) dstp[i] = vreg[i] * rs;
    }
}

// ---------------- one disentangle iteration (fused softmax + aggregate + residual + norm) ----
// Warp = one node. Lane = (factor k = lane&7, edge-slot j = lane>>3).
// Lane (k,j) accumulates numer/denom for factor k over edges e0+j, e0+j+4, ...
// with the next slot's index prefetched one trip ahead.
//   s = <h_dst[n,k], h_normed[d,k]>  (|s|<=1, so softmax needs no max-subtraction)
// Butterfly shfl_xor (8,16) sums the 4 edge-slots; lanes 0..7 finish:
//   out = l2norm(numer/denom + h_normed[n,k]).
__global__ __launch_bounds__(256) void attn_kernel(int iter, float* __restrict__ out_final) {
    int n = (blockIdx.x * blockDim.x + threadIdx.x) >> 5;
    if (n >= N_NODES) return;
    int lane = threadIdx.x & 31;
    int k = lane & 7;
    int j = lane >> 3;       // 0..3

    const float* hin  = (iter == 0) ? g_hn : ((iter == 1) ? g_b0 : g_b1);
    float*       hout = (iter == 0) ? g_b0 : ((iter == 1) ? g_b1 : out_final);

    const float4* hdr = reinterpret_cast<const float4*>(hin + (size_t)n * OUT_F + k * FD);
    float4 h0 = __ldg(hdr + 0);
    float4 h1 = __ldg(hdr + 1);

    float nu0 = 0.f, nu1 = 0.f, nu2 = 0.f, nu3 = 0.f;
    float nu4 = 0.f, nu5 = 0.f, nu6 = 0.f, nu7 = 0.f;
    float den = 0.f;

    int e0 = __ldg(&g_rowptr[n]);
    int e1 = __ldg(&g_rowptr[n + 1]);

    int e = e0 + j;
    int d_cur = (e < e1) ? __ldg(&g_csrdst[e]) : 0;
    for (; e < e1; e += 4) {
        // prefetch next trip's index while this trip's gather+math is in flight
        int d_nxt = (e + 4 < e1) ? __ldg(&g_csrdst[e + 4]) : 0;

        const float4* fp = reinterpret_cast<const float4*>(g_hn + (size_t)d_cur * OUT_F + k * FD);
        float4 f0 = __ldg(fp + 0);
        float4 f1 = __ldg(fp + 1);

        float s = h0.x * f0.x + h0.y * f0.y + h0.z * f0.z + h0.w * f0.w
                + h1.x * f1.x + h1.y * f1.y + h1.z * f1.z + h1.w * f1.w;
        float ex = __expf(s);
        den += ex;
        nu0 += ex * f0.x; nu1 += ex * f0.y; nu2 += ex * f0.z; nu3 += ex * f0.w;
        nu4 += ex * f1.x; nu5 += ex * f1.y; nu6 += ex * f1.z; nu7 += ex * f1.w;

        d_cur = d_nxt;
    }

    // butterfly reduce across the 4 edge-slots (lanes k, k+8, k+16, k+24)
    #pragma unroll
    for (int m = 8; m <= 16; m <<= 1) {
        den += __shfl_xor_sync(0xffffffffu, den, m);
        nu0 += __shfl_xor_sync(0xffffffffu, nu0, m);
        nu1 += __shfl_xor_sync(0xffffffffu, nu1, m);
        nu2 += __shfl_xor_sync(0xffffffffu, nu2, m);
        nu3 += __shfl_xor_sync(0xffffffffu, nu3, m);
        nu4 += __shfl_xor_sync(0xffffffffu, nu4, m);
        nu5 += __shfl_xor_sync(0xffffffffu, nu5, m);
        nu6 += __shfl_xor_sync(0xffffffffu, nu6, m);
        nu7 += __shfl_xor_sync(0xffffffffu, nu7, m);
    }

    if (lane < 8) {
        float inv = (e1 > e0) ? (1.0f / den) : 0.0f;

        const float4* hnr = reinterpret_cast<const float4*>(g_hn + (size_t)n * OUT_F + k * FD);
        float4 a0 = __ldg(hnr + 0);
        float4 a1 = __ldg(hnr + 1);

        float o0 = nu0 * inv + a0.x;
        float o1 = nu1 * inv + a0.y;
        float o2 = nu2 * inv + a0.z;
        float o3 = nu3 * inv + a0.w;
        float o4 = nu4 * inv + a1.x;
        float o5 = nu5 * inv + a1.y;
        float o6 = nu6 * inv + a1.z;
        float o7 = nu7 * inv + a1.w;

        float ss = o0*o0 + o1*o1 + o2*o2 + o3*o3 + o4*o4 + o5*o5 + o6*o6 + o7*o7;
        float r  = rsqrtf(ss);

        float4* op = reinterpret_cast<float4*>(hout + (size_t)n * OUT_F + k * FD);
        op[0] = make_float4(o0 * r, o1 * r, o2 * r, o3 * r);
        op[1] = make_float4(o4 * r, o5 * r, o6 * r, o7 * r);
    }
}

// ---------------- launch ----------------
extern "C" void kernel_launch(void* const* d_in, const int* in_sizes, int n_in,
                              void* d_out, int out_size) {
    const float* x    = (const float*)d_in[0];   // [40000,128]
    const float* w    = (const float*)d_in[1];   // [128,64]
    const float* bias = (const float*)d_in[2];   // [64]
    const int*   ei   = (const int*)d_in[3];     // [2,640000]
    const int*   src  = ei;
    const int*   dst  = ei + N_EDGES;
    float*       out  = (float*)d_out;           // [40000,64]

    // GEMM first (independent of CSR build)
    gemm_norm_kernel<<<N_NODES / 64, 256>>>(x, w, bias);

    zero_deg_kernel<<<(N_NODES + 255) / 256, 256>>>();
    hist_kernel<<<(N_EDGES + 255) / 256, 256>>>(src);
    scan_partial_kernel<<<N_PART, SCAN_BLK>>>();
    scan_part2_kernel<<<1, SCAN_BLK>>>();
    scan_apply_kernel<<<N_PART, SCAN_BLK>>>();
    scatter_kernel<<<(N_EDGES + 255) / 256, 256>>>(src, dst);

    // one warp per node: 40000 warps -> 5000 blocks of 256 threads
    int attn_blocks = (N_NODES * 32 + 255) / 256;
    attn_kernel<<<attn_blocks, 256>>>(0, out);
    attn_kernel<<<attn_blocks, 256>>>(1, out);
    attn_kernel<<<attn_blocks, 256>>>(2, out);
}

// round 9
// speedup vs baseline: 1.2830x; 1.0833x over previous
#include <cuda_runtime.h>
#include <cuda_fp16.h>

#define N_NODES 40000
#define N_EDGES 640000
#define IN_F    128
#define OUT_F   64
#define NK      8
#define FD      8

#define SCAN_BLK   256
#define N_PART     ((N_NODES + SCAN_BLK - 1) / SCAN_BLK)   // 157

// ---------------- persistent device scratch (no allocations allowed) ----------------
// ZERO INVARIANT: g_deg, g_scanstate, g_blkcounter are zero at entry of every
// kernel_launch call (statically zero-initialized; each call restores them:
// scan_onepass re-zeros g_deg, scatter re-zeros scanstate+counter).
__device__ int          g_deg[N_NODES];
__device__ int          g_rowptr[N_NODES + 1];
__device__ int          g_cursor[N_NODES];
__device__ int          g_csrdst[N_EDGES];
__device__ unsigned int g_blkcounter;
__device__ unsigned int g_scanstate[N_PART];     // packed: flag<<30 | value
__device__ float        g_hn[N_NODES * OUT_F];   // h_normed fp32 (residual + h_dst iter0)
__device__ __half       g_hnh[N_NODES * OUT_F];  // h_normed fp16 (per-edge gather table)
__device__ float        g_b0[N_NODES * OUT_F];   // h_dst ping
__device__ float        g_b1[N_NODES * OUT_F];   // h_dst pong

// block-level exclusive scan helper: returns exclusive prefix of v within the
// block; *total gets the block sum. 256 threads = 8 warps.
__device__ __forceinline__ int block_excl_scan(int v, int* total) {
    __shared__ int wsum[8];
    int lane = threadIdx.x & 31, wid = threadIdx.x >> 5;
    int incl = v;
    #pragma unroll
    for (int off = 1; off < 32; off <<= 1) {
        int u = __shfl_up_sync(0xffffffffu, incl, off);
        if (lane >= off) incl += u;
    }
    if (lane == 31) wsum[wid] = incl;
    __syncthreads();
    if (wid == 0) {
        int wi = (lane < 8) ? wsum[lane] : 0;
        #pragma unroll
        for (int off = 1; off < 8; off <<= 1) {
            int u = __shfl_up_sync(0xffffffffu, wi, off);
            if (lane >= off) wi += u;
        }
        if (lane < 8) wsum[lane] = wi;   // inclusive warp sums
    }
    __syncthreads();
    int warpoff = (wid > 0) ? wsum[wid - 1] : 0;
    *total = wsum[7];
    return warpoff + (incl - v);
}

// single-pass scan with decoupled lookback (ticket ordering; all 157 blocks co-resident).
// Consumes g_deg and RE-ZEROS it (restores the zero invariant for the next call).
__global__ void scan_onepass_kernel() {
    __shared__ int sbid;
    __shared__ int sexcl;
    if (threadIdx.x == 0) sbid = (int)atomicAdd(&g_blkcounter, 1u);
    __syncthreads();
    int bid = sbid;
    int i = bid * SCAN_BLK + threadIdx.x;
    int v = (i < N_NODES) ? g_deg[i] : 0;
    int total;
    int ex = block_excl_scan(v, &total);

    if (threadIdx.x == 0) {
        int excl = 0;
        if (bid == 0) {
            atomicExch(&g_scanstate[0], (2u << 30) | (unsigned)total);
        } else {
            atomicExch(&g_scanstate[bid], (1u << 30) | (unsigned)total);
            int p = bid - 1;
            while (p >= 0) {
                unsigned st;
                do { st = atomicAdd(&g_scanstate[p], 0u); } while ((st >> 30) == 0u);
                excl += (int)(st & 0x3FFFFFFFu);
                if ((st >> 30) == 2u) break;
                p--;
            }
            atomicExch(&g_scanstate[bid], (2u << 30) | (unsigned)(excl + total));
        }
        sexcl = excl;
        if (bid == N_PART - 1) g_rowptr[N_NODES] = excl + total;   // = N_EDGES
    }
    __syncthreads();
    if (i < N_NODES) {
        int val = sexcl + ex;
        g_rowptr[i] = val;
        g_cursor[i] = val;
        g_deg[i] = 0;                      // restore zero invariant
    }
}

// 1 edge per thread. Also resets scan state + ticket counter for the next call
// (ordered before the next replay's scan by stream order).
__global__ void scatter_kernel(const int* __restrict__ src, const int* __restrict__ dst) {
    int e = blockIdx.x * blockDim.x + threadIdx.x;
    if (blockIdx.x == 0) {
        if (threadIdx.x < N_PART) g_scanstate[threadIdx.x] = 0u;
        if (threadIdx.x == N_PART) g_blkcounter = 0u;
    }
    if (e < N_EDGES) {
        int s   = src[e];
        int pos = atomicAdd(&g_cursor[s], 1);
        g_csrdst[pos] = dst[e];
    }
}

// ---------------- fused GEMM + bias + leaky_relu + l2norm + EDGE HISTOGRAM ----------------
// 625 blocks x 256 threads = 160000 threads; each histograms 4 edges (int4 load +
// 4 fire-and-forget REDs) -- overlaps the atomic latency with the FMA mainloop.
// g_deg is zero at entry per the zero invariant.
__global__ __launch_bounds__(256) void gemm_norm_kernel(
        const float* __restrict__ x, const float* __restrict__ w,
        const float* __restrict__ bias, const int* __restrict__ src) {
    __shared__ float xs[64][65];   // x chunk 64 rows x 64 k (padded); reused as out tile
    __shared__ float ws[64][64];   // w chunk 64 k x 64 cols

    int t    = threadIdx.x;
    int row0 = blockIdx.x * 64;
    int tx   = t & 15;     // col group (4 cols)
    int ty   = t >> 4;     // row group (4 rows)

    // fused histogram: 4 edges per thread (covers N_EDGES exactly)
    {
        int q = blockIdx.x * 256 + t;           // 0..159999
        int4 s4 = __ldg(reinterpret_cast<const int4*>(src) + q);
        atomicAdd(&g_deg[s4.x], 1);
        atomicAdd(&g_deg[s4.y], 1);
        atomicAdd(&g_deg[s4.z], 1);
        atomicAdd(&g_deg[s4.w], 1);
    }

    float acc[4][4];
    #pragma unroll
    for (int i = 0; i < 4; i++)
        #pragma unroll
        for (int j = 0; j < 4; j++) acc[i][j] = 0.0f;

    for (int kc = 0; kc < IN_F; kc += 64) {
        #pragma unroll
        for (int i = 0; i < 4; i++) {
            int li = t + i * 256;           // 0..1023
            int r  = li >> 4;               // 0..63
            int c4 = li & 15;               // 0..15
            float4 v = *reinterpret_cast<const float4*>(x + (size_t)(row0 + r) * IN_F + kc + c4 * 4);
            xs[r][c4 * 4 + 0] = v.x; xs[r][c4 * 4 + 1] = v.y;
            xs[r][c4 * 4 + 2] = v.z; xs[r][c4 * 4 + 3] = v.w;
        }
        #pragma unroll
        for (int i = 0; i < 4; i++) {
            int li = t + i * 256;
            int r  = li >> 4;
            int c4 = li & 15;
            float4 v = *reinterpret_cast<const float4*>(w + (size_t)(kc + r) * OUT_F + c4 * 4);
            *reinterpret_cast<float4*>(&ws[r][c4 * 4]) = v;
        }
        __syncthreads();

        #pragma unroll
        for (int k = 0; k < 64; k++) {
            float4 b = *reinterpret_cast<const float4*>(&ws[k][tx * 4]);
            float a0 = xs[ty * 4 + 0][k];
            float a1 = xs[ty * 4 + 1][k];
            float a2 = xs[ty * 4 + 2][k];
            float a3 = xs[ty * 4 + 3][k];
            acc[0][0] += a0 * b.x; acc[0][1] += a0 * b.y; acc[0][2] += a0 * b.z; acc[0][3] += a0 * b.w;
            acc[1][0] += a1 * b.x; acc[1][1] += a1 * b.y; acc[1][2] += a1 * b.z; acc[1][3] += a1 * b.w;
            acc[2][0] += a2 * b.x; acc[2][1] += a2 * b.y; acc[2][2] += a2 * b.z; acc[2][3] += a2 * b.w;
            acc[3][0] += a3 * b.x; acc[3][1] += a3 * b.y; acc[3][2] += a3 * b.z; acc[3][3] += a3 * b.w;
        }
        __syncthreads();
    }

    // bias + leaky_relu into out tile (reuse xs)
    float4 bv = *reinterpret_cast<const float4*>(bias + tx * 4);
    float bb[4] = {bv.x, bv.y, bv.z, bv.w};
    #pragma unroll
    for (int i = 0; i < 4; i++)
        #pragma unroll
        for (int j = 0; j < 4; j++) {
            float v = acc[i][j] + bb[j];
            v = (v > 0.0f) ? v : 0.01f * v;
            xs[ty * 4 + i][tx * 4 + j] = v;
        }
    __syncthreads();

    // per-factor l2norm -> fp32 table (residual) + fp16 table (gathers)
    for (int p = t; p < 512; p += 256) {
        int r  = p >> 3;
        int kk = p & 7;
        float vreg[8];
        float ss = 0.0f;
        #pragma unroll
        for (int i = 0; i < 8; i++) {
            vreg[i] = xs[r][kk * 8 + i];
            ss += vreg[i] * vreg[i];
        }
        float rs = rsqrtf(ss);
        size_t off = (size_t)(row0 + r) * OUT_F + kk * 8;
        union { __half h[8]; uint4 u; } pk;
        #pragma unroll
        for (int i = 0; i < 8; i++) {
            float o = vreg[i] * rs;
            g_hn[off + i] = o;
            pk.h[i] = __float2half_rn(o);
        }
        *reinterpret_cast<uint4*>(g_hnh + off) = pk.u;
    }
}

// ---------------- one disentangle iteration (fused softmax + aggregate + residual + norm) ----
// Warp = one node. Lane = (factor k = lane&7, edge-slot j = lane>>3).
// Per-edge features gathered from the fp16 table (one LDG.128 per edge-factor);
// h_dst and residual stay fp32. Next trip's index prefetched.
// Butterfly shfl_xor (8,16) sums the 4 edge-slots; lanes 0..7 finish.
__global__ __launch_bounds__(256) void attn_kernel(int iter, float* __restrict__ out_final) {
    int n = (blockIdx.x * blockDim.x + threadIdx.x) >> 5;
    if (n >= N_NODES) return;
    int lane = threadIdx.x & 31;
    int k = lane & 7;
    int j = lane >> 3;       // 0..3

    const float* hin  = (iter == 0) ? g_hn : ((iter == 1) ? g_b0 : g_b1);
    float*       hout = (iter == 0) ? g_b0 : ((iter == 1) ? g_b1 : out_final);

    const float4* hdr = reinterpret_cast<const float4*>(hin + (size_t)n * OUT_F + k * FD);
    float4 h0 = __ldg(hdr + 0);
    float4 h1 = __ldg(hdr + 1);

    float nu0 = 0.f, nu1 = 0.f, nu2 = 0.f, nu3 = 0.f;
    float nu4 = 0.f, nu5 = 0.f, nu6 = 0.f, nu7 = 0.f;
    float den = 0.f;

    int e0 = __ldg(&g_rowptr[n]);
    int e1 = __ldg(&g_rowptr[n + 1]);

    int e = e0 + j;
    int d_cur = (e < e1) ? __ldg(&g_csrdst[e]) : 0;
    for (; e < e1; e += 4) {
        // prefetch next trip's index while this trip's gather+math is in flight
        int d_nxt = (e + 4 < e1) ? __ldg(&g_csrdst[e + 4]) : 0;

        const uint4* fp = reinterpret_cast<const uint4*>(g_hnh + (size_t)d_cur * OUT_F + k * FD);
        uint4 q = __ldg(fp);
        float2 fa = __half22float2(*reinterpret_cast<const __half2*>(&q.x));
        float2 fb = __half22float2(*reinterpret_cast<const __half2*>(&q.y));
        float2 fc = __half22float2(*reinterpret_cast<const __half2*>(&q.z));
        float2 fd = __half22float2(*reinterpret_cast<const __half2*>(&q.w));

        float s = h0.x * fa.x + h0.y * fa.y + h0.z * fb.x + h0.w * fb.y
                + h1.x * fc.x + h1.y * fc.y + h1.z * fd.x + h1.w * fd.y;
        float ex = __expf(s);
        den += ex;
        nu0 += ex * fa.x; nu1 += ex * fa.y; nu2 += ex * fb.x; nu3 += ex * fb.y;
        nu4 += ex * fc.x; nu5 += ex * fc.y; nu6 += ex * fd.x; nu7 += ex * fd.y;

        d_cur = d_nxt;
    }

    // butterfly reduce across the 4 edge-slots (lanes k, k+8, k+16, k+24)
    #pragma unroll
    for (int m = 8; m <= 16; m <<= 1) {
        den += __shfl_xor_sync(0xffffffffu, den, m);
        nu0 += __shfl_xor_sync(0xffffffffu, nu0, m);
        nu1 += __shfl_xor_sync(0xffffffffu, nu1, m);
        nu2 += __shfl_xor_sync(0xffffffffu, nu2, m);
        nu3 += __shfl_xor_sync(0xffffffffu, nu3, m);
        nu4 += __shfl_xor_sync(0xffffffffu, nu4, m);
        nu5 += __shfl_xor_sync(0xffffffffu, nu5, m);
        nu6 += __shfl_xor_sync(0xffffffffu, nu6, m);
        nu7 += __shfl_xor_sync(0xffffffffu, nu7, m);
    }

    if (lane < 8) {
        float inv = (e1 > e0) ? (1.0f / den) : 0.0f;

        const float4* hnr = reinterpret_cast<const float4*>(g_hn + (size_t)n * OUT_F + k * FD);
        float4 a0 = __ldg(hnr + 0);
        float4 a1 = __ldg(hnr + 1);

        float o0 = nu0 * inv + a0.x;
        float o1 = nu1 * inv + a0.y;
        float o2 = nu2 * inv + a0.z;
        float o3 = nu3 * inv + a0.w;
        float o4 = nu4 * inv + a1.x;
        float o5 = nu5 * inv + a1.y;
        float o6 = nu6 * inv + a1.z;
        float o7 = nu7 * inv + a1.w;

        float ss = o0*o0 + o1*o1 + o2*o2 + o3*o3 + o4*o4 + o5*o5 + o6*o6 + o7*o7;
        float r  = rsqrtf(ss);

        float4* op = reinterpret_cast<float4*>(hout + (size_t)n * OUT_F + k * FD);
        op[0] = make_float4(o0 * r, o1 * r, o2 * r, o3 * r);
        op[1] = make_float4(o4 * r, o5 * r, o6 * r, o7 * r);
    }
}

// ---------------- launch ----------------
extern "C" void kernel_launch(void* const* d_in, const int* in_sizes, int n_in,
                              void* d_out, int out_size) {
    const float* x    = (const float*)d_in[0];   // [40000,128]
    const float* w    = (const float*)d_in[1];   // [128,64]
    const float* bias = (const float*)d_in[2];   // [64]
    const int*   ei   = (const int*)d_in[3];     // [2,640000]
    const int*   src  = ei;
    const int*   dst  = ei + N_EDGES;
    float*       out  = (float*)d_out;           // [40000,64]

    // GEMM + fused edge histogram (g_deg zero by invariant)
    gemm_norm_kernel<<<N_NODES / 64, 256>>>(x, w, bias, src);

    scan_onepass_kernel<<<N_PART, SCAN_BLK>>>();   // also re-zeros g_deg
    scatter_kernel<<<(N_EDGES + 255) / 256, 256>>>(src, dst);  // also resets scan state

    // one warp per node: 40000 warps -> 5000 blocks of 256 threads
    int attn_blocks = (N_NODES * 32 + 255) / 256;
    attn_kernel<<<attn_blocks, 256>>>(0, out);
    attn_kernel<<<attn_blocks, 256>>>(1, out);
    attn_kernel<<<attn_blocks, 256>>>(2, out);
}

// round 10
// speedup vs baseline: 1.3525x; 1.0542x over previous
#include <cuda_runtime.h>
#include <cuda_fp16.h>

#define N_NODES 40000
#define N_EDGES 640000
#define IN_F    128
#define OUT_F   64
#define NK      8
#define FD      8

#define SCAN_BLK   256
#define N_PART     ((N_NODES + SCAN_BLK - 1) / SCAN_BLK)   // 157

// ---------------- persistent device scratch (no allocations allowed) ----------------
// ZERO INVARIANT: g_deg, g_scanstate, g_blkcounter are zero at entry of every
// kernel_launch call (statically zero-initialized; each call restores them:
// scan_onepass re-zeros g_deg, scatter re-zeros scanstate+counter).
__device__ int          g_deg[N_NODES];
__device__ int          g_rowptr[N_NODES + 1];
__device__ int          g_cursor[N_NODES];
__device__ int          g_csrdst[N_EDGES];
__device__ unsigned int g_blkcounter;
__device__ unsigned int g_scanstate[N_PART];     // packed: flag<<30 | value
__device__ float        g_hn[N_NODES * OUT_F];   // h_normed fp32 (residual + h_dst iter0)
__device__ __half       g_hnh[N_NODES * OUT_F];  // h_normed fp16 (per-edge gather table)
__device__ float        g_b0[N_NODES * OUT_F];   // h_dst ping
__device__ float        g_b1[N_NODES * OUT_F];   // h_dst pong

// block-level exclusive scan helper: returns exclusive prefix of v within the
// block; *total gets the block sum. 256 threads = 8 warps.
__device__ __forceinline__ int block_excl_scan(int v, int* total) {
    __shared__ int wsum[8];
    int lane = threadIdx.x & 31, wid = threadIdx.x >> 5;
    int incl = v;
    #pragma unroll
    for (int off = 1; off < 32; off <<= 1) {
        int u = __shfl_up_sync(0xffffffffu, incl, off);
        if (lane >= off) incl += u;
    }
    if (lane == 31) wsum[wid] = incl;
    __syncthreads();
    if (wid == 0) {
        int wi = (lane < 8) ? wsum[lane] : 0;
        #pragma unroll
        for (int off = 1; off < 8; off <<= 1) {
            int u = __shfl_up_sync(0xffffffffu, wi, off);
            if (lane >= off) wi += u;
        }
        if (lane < 8) wsum[lane] = wi;   // inclusive warp sums
    }
    __syncthreads();
    int warpoff = (wid > 0) ? wsum[wid - 1] : 0;
    *total = wsum[7];
    return warpoff + (incl - v);
}

// single-pass scan with decoupled lookback (ticket ordering; all 157 blocks co-resident).
// Consumes g_deg and RE-ZEROS it (restores the zero invariant for the next call).
__global__ void scan_onepass_kernel() {
    __shared__ int sbid;
    __shared__ int sexcl;
    if (threadIdx.x == 0) sbid = (int)atomicAdd(&g_blkcounter, 1u);
    __syncthreads();
    int bid = sbid;
    int i = bid * SCAN_BLK + threadIdx.x;
    int v = (i < N_NODES) ? g_deg[i] : 0;
    int total;
    int ex = block_excl_scan(v, &total);

    if (threadIdx.x == 0) {
        int excl = 0;
        if (bid == 0) {
            atomicExch(&g_scanstate[0], (2u << 30) | (unsigned)total);
        } else {
            atomicExch(&g_scanstate[bid], (1u << 30) | (unsigned)total);
            int p = bid - 1;
            while (p >= 0) {
                unsigned st;
                do { st = atomicAdd(&g_scanstate[p], 0u); } while ((st >> 30) == 0u);
                excl += (int)(st & 0x3FFFFFFFu);
                if ((st >> 30) == 2u) break;
                p--;
            }
            atomicExch(&g_scanstate[bid], (2u << 30) | (unsigned)(excl + total));
        }
        sexcl = excl;
        if (bid == N_PART - 1) g_rowptr[N_NODES] = excl + total;   // = N_EDGES
    }
    __syncthreads();
    if (i < N_NODES) {
        int val = sexcl + ex;
        g_rowptr[i] = val;
        g_cursor[i] = val;
        g_deg[i] = 0;                      // restore zero invariant
    }
}

// 1 edge per thread. Also resets scan state + ticket counter for the next call
// (ordered before the next replay's scan by stream order).
__global__ void scatter_kernel(const int* __restrict__ src, const int* __restrict__ dst) {
    int e = blockIdx.x * blockDim.x + threadIdx.x;
    if (blockIdx.x == 0) {
        if (threadIdx.x < N_PART) g_scanstate[threadIdx.x] = 0u;
        if (threadIdx.x == N_PART) g_blkcounter = 0u;
    }
    if (e < N_EDGES) {
        int s   = src[e];
        int pos = atomicAdd(&g_cursor[s], 1);
        g_csrdst[pos] = dst[e];
    }
}

// ---------------- fused GEMM + bias + leaky_relu + l2norm + EDGE HISTOGRAM ----------------
// 625 blocks x 256 threads = 160000 threads; each histograms 4 edges (int4 load +
// 4 fire-and-forget REDs) -- overlaps the atomic latency with the FMA mainloop.
// g_deg is zero at entry per the zero invariant.
__global__ __launch_bounds__(256) void gemm_norm_kernel(
        const float* __restrict__ x, const float* __restrict__ w,
        const float* __restrict__ bias, const int* __restrict__ src) {
    __shared__ float xs[64][65];   // x chunk 64 rows x 64 k (padded); reused as out tile
    __shared__ float ws[64][64];   // w chunk 64 k x 64 cols

    int t    = threadIdx.x;
    int row0 = blockIdx.x * 64;
    int tx   = t & 15;     // col group (4 cols)
    int ty   = t >> 4;     // row group (4 rows)

    // fused histogram: 4 edges per thread (covers N_EDGES exactly)
    {
        int q = blockIdx.x * 256 + t;           // 0..159999
        int4 s4 = __ldg(reinterpret_cast<const int4*>(src) + q);
        atomicAdd(&g_deg[s4.x], 1);
        atomicAdd(&g_deg[s4.y], 1);
        atomicAdd(&g_deg[s4.z], 1);
        atomicAdd(&g_deg[s4.w], 1);
    }

    float acc[4][4];
    #pragma unroll
    for (int i = 0; i < 4; i++)
        #pragma unroll
        for (int j = 0; j < 4; j++) acc[i][j] = 0.0f;

    for (int kc = 0; kc < IN_F; kc += 64) {
        #pragma unroll
        for (int i = 0; i < 4; i++) {
            int li = t + i * 256;           // 0..1023
            int r  = li >> 4;               // 0..63
            int c4 = li & 15;               // 0..15
            float4 v = *reinterpret_cast<const float4*>(x + (size_t)(row0 + r) * IN_F + kc + c4 * 4);
            xs[r][c4 * 4 + 0] = v.x; xs[r][c4 * 4 + 1] = v.y;
            xs[r][c4 * 4 + 2] = v.z; xs[r][c4 * 4 + 3] = v.w;
        }
        #pragma unroll
        for (int i = 0; i < 4; i++) {
            int li = t + i * 256;
            int r  = li >> 4;
            int c4 = li & 15;
            float4 v = *reinterpret_cast<const float4*>(w + (size_t)(kc + r) * OUT_F + c4 * 4);
            *reinterpret_cast<float4*>(&ws[r][c4 * 4]) = v;
        }
        __syncthreads();

        #pragma unroll
        for (int k = 0; k < 64; k++) {
            float4 b = *reinterpret_cast<const float4*>(&ws[k][tx * 4]);
            float a0 = xs[ty * 4 + 0][k];
            float a1 = xs[ty * 4 + 1][k];
            float a2 = xs[ty * 4 + 2][k];
            float a3 = xs[ty * 4 + 3][k];
            acc[0][0] += a0 * b.x; acc[0][1] += a0 * b.y; acc[0][2] += a0 * b.z; acc[0][3] += a0 * b.w;
            acc[1][0] += a1 * b.x; acc[1][1] += a1 * b.y; acc[1][2] += a1 * b.z; acc[1][3] += a1 * b.w;
            acc[2][0] += a2 * b.x; acc[2][1] += a2 * b.y; acc[2][2] += a2 * b.z; acc[2][3] += a2 * b.w;
            acc[3][0] += a3 * b.x; acc[3][1] += a3 * b.y; acc[3][2] += a3 * b.z; acc[3][3] += a3 * b.w;
        }
        __syncthreads();
    }

    // bias + leaky_relu into out tile (reuse xs)
    float4 bv = *reinterpret_cast<const float4*>(bias + tx * 4);
    float bb[4] = {bv.x, bv.y, bv.z, bv.w};
    #pragma unroll
    for (int i = 0; i < 4; i++)
        #pragma unroll
        for (int j = 0; j < 4; j++) {
            float v = acc[i][j] + bb[j];
            v = (v > 0.0f) ? v : 0.01f * v;
            xs[ty * 4 + i][tx * 4 + j] = v;
        }
    __syncthreads();

    // per-factor l2norm -> fp32 table (residual) + fp16 table (gathers)
    for (int p = t; p < 512; p += 256) {
        int r  = p >> 3;
        int kk = p & 7;
        float vreg[8];
        float ss = 0.0f;
        #pragma unroll
        for (int i = 0; i < 8; i++) {
            vreg[i] = xs[r][kk * 8 + i];
            ss += vreg[i] * vreg[i];
        }
        float rs = rsqrtf(ss);
        size_t off = (size_t)(row0 + r) * OUT_F + kk * 8;
        union { __half h[8]; uint4 u; } pk;
        #pragma unroll
        for (int i = 0; i < 8; i++) {
            float o = vreg[i] * rs;
            g_hn[off + i] = o;
            pk.h[i] = __float2half_rn(o);
        }
        *reinterpret_cast<uint4*>(g_hnh + off) = pk.u;
    }
}

// ---------------- one disentangle iteration (fused softmax + aggregate + residual + norm) ----
// Warp = one node. Lane = (factor k = lane&7, edge-slot j = lane>>3).
// 2-edge unroll per lane (e0+j and e0+j+4 per trip, stride 8): halves loop
// overhead, doubles gathers in flight. launch_bounds(256,6) caps regs at 40
// -> 6 blocks/SM = 75% occupancy (was 4 blocks/50% at 48 regs, issue=54.5%).
// Butterfly shfl_xor (8,16) sums the 4 edge-slots; lanes 0..7 finish.
__global__ __launch_bounds__(256, 6) void attn_kernel(int iter, float* __restrict__ out_final) {
    int n = (blockIdx.x * blockDim.x + threadIdx.x) >> 5;
    if (n >= N_NODES) return;
    int lane = threadIdx.x & 31;
    int k = lane & 7;
    int j = lane >> 3;       // 0..3

    const float* hin  = (iter == 0) ? g_hn : ((iter == 1) ? g_b0 : g_b1);
    float*       hout = (iter == 0) ? g_b0 : ((iter == 1) ? g_b1 : out_final);

    const float4* hdr = reinterpret_cast<const float4*>(hin + (size_t)n * OUT_F + k * FD);
    float4 h0 = __ldg(hdr + 0);
    float4 h1 = __ldg(hdr + 1);

    float nu0 = 0.f, nu1 = 0.f, nu2 = 0.f, nu3 = 0.f;
    float nu4 = 0.f, nu5 = 0.f, nu6 = 0.f, nu7 = 0.f;
    float den = 0.f;

    int e0 = __ldg(&g_rowptr[n]);
    int e1 = __ldg(&g_rowptr[n + 1]);

    int e = e0 + j;
    // main loop: two edges per trip (e and e+4)
    for (; e + 4 < e1; e += 8) {
        int da = __ldg(&g_csrdst[e]);
        int db = __ldg(&g_csrdst[e + 4]);
        uint4 qa = __ldg(reinterpret_cast<const uint4*>(g_hnh + (size_t)da * OUT_F + k * FD));
        uint4 qb = __ldg(reinterpret_cast<const uint4*>(g_hnh + (size_t)db * OUT_F + k * FD));

        float2 aa = __half22float2(*reinterpret_cast<const __half2*>(&qa.x));
        float2 ab = __half22float2(*reinterpret_cast<const __half2*>(&qa.y));
        float2 ac = __half22float2(*reinterpret_cast<const __half2*>(&qa.z));
        float2 ad = __half22float2(*reinterpret_cast<const __half2*>(&qa.w));
        float sa = h0.x * aa.x + h0.y * aa.y + h0.z * ab.x + h0.w * ab.y
                 + h1.x * ac.x + h1.y * ac.y + h1.z * ad.x + h1.w * ad.y;
        float exa = __expf(sa);
        den += exa;
        nu0 += exa * aa.x; nu1 += exa * aa.y; nu2 += exa * ab.x; nu3 += exa * ab.y;
        nu4 += exa * ac.x; nu5 += exa * ac.y; nu6 += exa * ad.x; nu7 += exa * ad.y;

        float2 ba = __half22float2(*reinterpret_cast<const __half2*>(&qb.x));
        float2 bb = __half22float2(*reinterpret_cast<const __half2*>(&qb.y));
        float2 bc = __half22float2(*reinterpret_cast<const __half2*>(&qb.z));
        float2 bd = __half22float2(*reinterpret_cast<const __half2*>(&qb.w));
        float sb = h0.x * ba.x + h0.y * ba.y + h0.z * bb.x + h0.w * bb.y
                 + h1.x * bc.x + h1.y * bc.y + h1.z * bd.x + h1.w * bd.y;
        float exb = __expf(sb);
        den += exb;
        nu0 += exb * ba.x; nu1 += exb * ba.y; nu2 += exb * bb.x; nu3 += exb * bb.y;
        nu4 += exb * bc.x; nu5 += exb * bc.y; nu6 += exb * bd.x; nu7 += exb * bd.y;
    }
    // tail: at most one edge left for this lane
    if (e < e1) {
        int d = __ldg(&g_csrdst[e]);
        uint4 q = __ldg(reinterpret_cast<const uint4*>(g_hnh + (size_t)d * OUT_F + k * FD));
        float2 fa = __half22float2(*reinterpret_cast<const __half2*>(&q.x));
        float2 fb = __half22float2(*reinterpret_cast<const __half2*>(&q.y));
        float2 fc = __half22float2(*reinterpret_cast<const __half2*>(&q.z));
        float2 fd = __half22float2(*reinterpret_cast<const __half2*>(&q.w));
        float s = h0.x * fa.x + h0.y * fa.y + h0.z * fb.x + h0.w * fb.y
                + h1.x * fc.x + h1.y * fc.y + h1.z * fd.x + h1.w * fd.y;
        float ex = __expf(s);
        den += ex;
        nu0 += ex * fa.x; nu1 += ex * fa.y; nu2 += ex * fb.x; nu3 += ex * fb.y;
        nu4 += ex * fc.x; nu5 += ex * fc.y; nu6 += ex * fd.x; nu7 += ex * fd.y;
    }

    // butterfly reduce across the 4 edge-slots (lanes k, k+8, k+16, k+24)
    #pragma unroll
    for (int m = 8; m <= 16; m <<= 1) {
        den += __shfl_xor_sync(0xffffffffu, den, m);
        nu0 += __shfl_xor_sync(0xffffffffu, nu0, m);
        nu1 += __shfl_xor_sync(0xffffffffu, nu1, m);
        nu2 += __shfl_xor_sync(0xffffffffu, nu2, m);
        nu3 += __shfl_xor_sync(0xffffffffu, nu3, m);
        nu4 += __shfl_xor_sync(0xffffffffu, nu4, m);
        nu5 += __shfl_xor_sync(0xffffffffu, nu5, m);
        nu6 += __shfl_xor_sync(0xffffffffu, nu6, m);
        nu7 += __shfl_xor_sync(0xffffffffu, nu7, m);
    }

    if (lane < 8) {
        float inv = (e1 > e0) ? (1.0f / den) : 0.0f;

        const float4* hnr = reinterpret_cast<const float4*>(g_hn + (size_t)n * OUT_F + k * FD);
        float4 a0 = __ldg(hnr + 0);
        float4 a1 = __ldg(hnr + 1);

        float o0 = nu0 * inv + a0.x;
        float o1 = nu1 * inv + a0.y;
        float o2 = nu2 * inv + a0.z;
        float o3 = nu3 * inv + a0.w;
        float o4 = nu4 * inv + a1.x;
        float o5 = nu5 * inv + a1.y;
        float o6 = nu6 * inv + a1.z;
        float o7 = nu7 * inv + a1.w;

        float ss = o0*o0 + o1*o1 + o2*o2 + o3*o3 + o4*o4 + o5*o5 + o6*o6 + o7*o7;
        float r  = rsqrtf(ss);

        float4* op = reinterpret_cast<float4*>(hout + (size_t)n * OUT_F + k * FD);
        op[0] = make_float4(o0 * r, o1 * r, o2 * r, o3 * r);
        op[1] = make_float4(o4 * r, o5 * r, o6 * r, o7 * r);
    }
}

// ---------------- launch ----------------
extern "C" void kernel_launch(void* const* d_in, const int* in_sizes, int n_in,
                              void* d_out, int out_size) {
    const float* x    = (const float*)d_in[0];   // [40000,128]
    const float* w    = (const float*)d_in[1];   // [128,64]
    const float* bias = (const float*)d_in[2];   // [64]
    const int*   ei   = (const int*)d_in[3];     // [2,640000]
    const int*   src  = ei;
    const int*   dst  = ei + N_EDGES;
    float*       out  = (float*)d_out;           // [40000,64]

    // GEMM + fused edge histogram (g_deg zero by invariant)
    gemm_norm_kernel<<<N_NODES / 64, 256>>>(x, w, bias, src);

    scan_onepass_kernel<<<N_PART, SCAN_BLK>>>();   // also re-zeros g_deg
    scatter_kernel<<<(N_EDGES + 255) / 256, 256>>>(src, dst);  // also resets scan state

    // one warp per node: 40000 warps -> 5000 blocks of 256 threads
    int attn_blocks = (N_NODES * 32 + 255) / 256;
    attn_kernel<<<attn_blocks, 256>>>(0, out);
    attn_kernel<<<attn_blocks, 256>>>(1, out);
    attn_kernel<<<attn_blocks, 256>>>(2, out);
}